// round 3
// baseline (speedup 1.0000x reference)
#include <cuda_runtime.h>
#include <cstdint>

#define NROWS 8192
#define FDIM  512
#define HDIM  512
#define CDIM  64
#define MAXNZ 128
#define KRANK 278529u   // 1 + round(0.5*(557056-1)), banker's rounding
#define NS0   262144
#define NS1   262144
#define NS2   32768
#define NSTOT 557056

// ---------------- device scratch (static: no allocations allowed) ----------------
__device__ float g_W0m[HDIM*FDIM];
__device__ float g_W1m[HDIM*HDIM];
__device__ float g_W2m[CDIM*HDIM];
__device__ float g_h0[(size_t)NROWS*HDIM];
__device__ float g_h1[(size_t)NROWS*HDIM];
__device__ float g_h2[(size_t)NROWS*HDIM];
__device__ float g_hC[(size_t)NROWS*CDIM];
__device__ int   g_cols[NROWS*MAXNZ];
__device__ int   g_cnt[NROWS];
__device__ float g_dinv[NROWS];
__device__ unsigned g_hist1[32768];
__device__ unsigned g_hist2[65536];
__device__ unsigned g_selbin;
__device__ unsigned g_rank2;
__device__ float g_thr;
__device__ float g_part[128*HDIM];
__device__ float g_partsq[128];
__device__ float g_mu[HDIM];
__device__ float g_invrnm;

// ---------------- CSR build: one pass over dense adj, deterministic ----------------
// Block = one row. 256 threads, interleaved float4 chunks (coalesced), two scans
// of the row (second hits L1). Column order fixed by (chunk, lane) mapping.
__global__ __launch_bounds__(256) void build_csr(const float* __restrict__ adj) {
    int r = blockIdx.x;
    int t = threadIdx.x;
    const float4* row4 = (const float4*)(adj + (size_t)r * NROWS);

    int cnt = 0;
    #pragma unroll
    for (int q = 0; q < 8; q++) {
        int i4 = q * 256 + t;
        float4 v = row4[i4];
        int c0 = i4 * 4;
        cnt += (v.x != 0.0f || c0 + 0 == r);
        cnt += (v.y != 0.0f || c0 + 1 == r);
        cnt += (v.z != 0.0f || c0 + 2 == r);
        cnt += (v.w != 0.0f || c0 + 3 == r);
    }
    __shared__ int s[256];
    s[t] = cnt;
    __syncthreads();
    for (int off = 1; off < 256; off <<= 1) {
        int v = (t >= off) ? s[t - off] : 0;
        __syncthreads();
        s[t] += v;
        __syncthreads();
    }
    int excl = s[t] - cnt;
    int total = s[255];
    int w = excl;
    #pragma unroll
    for (int q = 0; q < 8; q++) {
        int i4 = q * 256 + t;
        float4 v = row4[i4];
        int c0 = i4 * 4;
        if ((v.x != 0.0f || c0 + 0 == r) && w < MAXNZ) g_cols[r * MAXNZ + w++] = c0 + 0;
        if ((v.y != 0.0f || c0 + 1 == r) && w < MAXNZ) g_cols[r * MAXNZ + w++] = c0 + 1;
        if ((v.z != 0.0f || c0 + 2 == r) && w < MAXNZ) g_cols[r * MAXNZ + w++] = c0 + 2;
        if ((v.w != 0.0f || c0 + 3 == r) && w < MAXNZ) g_cols[r * MAXNZ + w++] = c0 + 3;
    }
    if (t == 0) {
        g_cnt[r]  = (total < MAXNZ) ? total : MAXNZ;
        g_dinv[r] = rsqrtf((float)total);   // total >= 1 (self loop)
    }
}

// ---------------- exact radix-select threshold ----------------
__global__ void clear_hist() {
    int i = blockIdx.x * blockDim.x + threadIdx.x;
    if (i < 32768) g_hist1[i] = 0u;
    if (i < 65536) g_hist2[i] = 0u;
}

__device__ __forceinline__ float pick_score(const float* S0, const float* S1, const float* S2, int i) {
    if (i < NS0) return S0[i];
    if (i < NS0 + NS1) return S1[i - NS0];
    return S2[i - NS0 - NS1];
}

__global__ void hist1_k(const float* __restrict__ S0, const float* __restrict__ S1, const float* __restrict__ S2) {
    for (int i = blockIdx.x * blockDim.x + threadIdx.x; i < NSTOT; i += gridDim.x * blockDim.x) {
        unsigned bits = __float_as_uint(fabsf(pick_score(S0, S1, S2, i)));
        atomicAdd(&g_hist1[bits >> 16], 1u);
    }
}

__global__ __launch_bounds__(1024) void find_bin() {
    int t = threadIdx.x;  // 1024 threads, 32 bins each
    unsigned s = 0;
    for (int i = 0; i < 32; i++) s += g_hist1[t * 32 + i];
    __shared__ unsigned sh[1024];
    sh[t] = s;
    __syncthreads();
    for (int off = 1; off < 1024; off <<= 1) {
        unsigned v = (t >= off) ? sh[t - off] : 0u;
        __syncthreads();
        sh[t] += v;
        __syncthreads();
    }
    unsigned incl = sh[t], excl = incl - s;
    if (excl < KRANK && incl >= KRANK) {
        unsigned cum = excl;
        for (int i = 0; i < 32; i++) {
            unsigned c = g_hist1[t * 32 + i];
            if (cum + c >= KRANK) { g_selbin = (unsigned)(t * 32 + i); g_rank2 = KRANK - cum; break; }
            cum += c;
        }
    }
}

__global__ void hist2_k(const float* __restrict__ S0, const float* __restrict__ S1, const float* __restrict__ S2) {
    unsigned bin = g_selbin;
    for (int i = blockIdx.x * blockDim.x + threadIdx.x; i < NSTOT; i += gridDim.x * blockDim.x) {
        unsigned bits = __float_as_uint(fabsf(pick_score(S0, S1, S2, i)));
        if ((bits >> 16) == bin) atomicAdd(&g_hist2[bits & 0xFFFFu], 1u);
    }
}

__global__ __launch_bounds__(1024) void find_thr() {
    int t = threadIdx.x;  // 1024 threads, 64 bins each
    unsigned target = g_rank2, bin = g_selbin;
    unsigned s = 0;
    for (int i = 0; i < 64; i++) s += g_hist2[t * 64 + i];
    __shared__ unsigned sh[1024];
    sh[t] = s;
    __syncthreads();
    for (int off = 1; off < 1024; off <<= 1) {
        unsigned v = (t >= off) ? sh[t - off] : 0u;
        __syncthreads();
        sh[t] += v;
        __syncthreads();
    }
    unsigned incl = sh[t], excl = incl - s;
    if (excl < target && incl >= target) {
        unsigned cum = excl;
        for (int i = 0; i < 64; i++) {
            unsigned c = g_hist2[t * 64 + i];
            if (cum + c >= target) {
                g_thr = __uint_as_float((bin << 16) | (unsigned)(t * 64 + i));
                break;
            }
            cum += c;
        }
    }
}

// ---------------- masked weights ----------------
__global__ void mask_k(const float* __restrict__ W, const float* __restrict__ S,
                       float* __restrict__ Wm, int n) {
    float thr = g_thr;
    for (int i = blockIdx.x * blockDim.x + threadIdx.x; i < n; i += gridDim.x * blockDim.x)
        Wm[i] = (fabsf(S[i]) > thr) ? W[i] : 0.0f;
}

// ---------------- SGEMM: C[M,Nn] = A[M,K] * B[Nn,K]^T (fp32) ----------------
template<int BM, int BN, int BK, int TM, int TN>
__global__ __launch_bounds__(256) void sgemm_nt(const float* __restrict__ A,
                                                const float* __restrict__ B,
                                                float* __restrict__ Cmat,
                                                int M, int Nn, int K) {
    __shared__ float As[BK][BM];
    __shared__ float Bs[BK][BN];
    const int tid = threadIdx.x;
    const int brow = blockIdx.y * BM;
    const int bcol = blockIdx.x * BN;
    constexpr int TX = BN / TN;            // threads along N
    const int tx = tid % TX;
    const int ty = tid / TX;               // ty*TM spans BM

    float acc[TM][TN];
    #pragma unroll
    for (int m = 0; m < TM; m++)
        #pragma unroll
        for (int n = 0; n < TN; n++) acc[m][n] = 0.0f;

    for (int kt = 0; kt < K; kt += BK) {
        #pragma unroll
        for (int i = tid; i < BM * BK / 4; i += 256) {
            int rowi = i / (BK / 4), kq = i % (BK / 4);
            float4 v = *(const float4*)(A + (size_t)(brow + rowi) * K + kt + kq * 4);
            As[kq * 4 + 0][rowi] = v.x; As[kq * 4 + 1][rowi] = v.y;
            As[kq * 4 + 2][rowi] = v.z; As[kq * 4 + 3][rowi] = v.w;
        }
        #pragma unroll
        for (int i = tid; i < BN * BK / 4; i += 256) {
            int rowi = i / (BK / 4), kq = i % (BK / 4);
            float4 v = *(const float4*)(B + (size_t)(bcol + rowi) * K + kt + kq * 4);
            Bs[kq * 4 + 0][rowi] = v.x; Bs[kq * 4 + 1][rowi] = v.y;
            Bs[kq * 4 + 2][rowi] = v.z; Bs[kq * 4 + 3][rowi] = v.w;
        }
        __syncthreads();
        #pragma unroll
        for (int k = 0; k < BK; k++) {
            float a[TM], b[TN];
            #pragma unroll
            for (int m = 0; m < TM; m++) a[m] = As[k][ty * TM + m];
            #pragma unroll
            for (int n = 0; n < TN; n++) b[n] = Bs[k][tx * TN + n];
            #pragma unroll
            for (int m = 0; m < TM; m++)
                #pragma unroll
                for (int n = 0; n < TN; n++) acc[m][n] = fmaf(a[m], b[n], acc[m][n]);
        }
        __syncthreads();
    }
    #pragma unroll
    for (int m = 0; m < TM; m++) {
        float* cp = Cmat + (size_t)(brow + ty * TM + m) * Nn + bcol + tx * TN;
        #pragma unroll
        for (int n = 0; n < TN; n++) cp[n] = acc[m][n];
    }
}

// ---------------- SpMM: out[r,:] = d_r * sum_j d_j * h[j,:] ----------------
__global__ __launch_bounds__(256) void spmm512(const float* __restrict__ hin, float* __restrict__ hout) {
    int r = blockIdx.x, t = threadIdx.x;
    __shared__ int   sc[MAXNZ];
    __shared__ float sw[MAXNZ];
    int cnt = g_cnt[r];
    for (int i = t; i < cnt; i += 256) {
        int j = g_cols[r * MAXNZ + i];
        sc[i] = j;
        sw[i] = g_dinv[j];
    }
    __syncthreads();
    float a0 = 0.0f, a1 = 0.0f;
    for (int k = 0; k < cnt; k++) {
        const float* hp = hin + (size_t)sc[k] * HDIM;
        float w = sw[k];
        a0 = fmaf(w, hp[t], a0);
        a1 = fmaf(w, hp[t + 256], a1);
    }
    float di = g_dinv[r];
    hout[(size_t)r * HDIM + t] = di * a0;
    hout[(size_t)r * HDIM + t + 256] = di * a1;
}

__global__ __launch_bounds__(64) void spmm64(const float* __restrict__ hin, float* __restrict__ hout) {
    int r = blockIdx.x, t = threadIdx.x;
    __shared__ int   sc[MAXNZ];
    __shared__ float sw[MAXNZ];
    int cnt = g_cnt[r];
    for (int i = t; i < cnt; i += 64) {
        int j = g_cols[r * MAXNZ + i];
        sc[i] = j;
        sw[i] = g_dinv[j];
    }
    __syncthreads();
    float a = 0.0f;
    for (int k = 0; k < cnt; k++)
        a = fmaf(sw[k], hin[(size_t)sc[k] * CDIM + t], a);
    hout[(size_t)r * CDIM + t] = g_dinv[r] * a;
}

// ---------------- PairNorm stats (deterministic two-stage) ----------------
__global__ __launch_bounds__(256) void colstats(const float* __restrict__ h) {
    int b = blockIdx.x, t = threadIdx.x;      // 128 blocks x 64 rows
    float s0 = 0.0f, s1 = 0.0f, sq = 0.0f;
    for (int r0 = 0; r0 < 64; r0++) {
        size_t r = (size_t)b * 64 + r0;
        float v0 = h[r * HDIM + t];
        float v1 = h[r * HDIM + t + 256];
        s0 += v0; s1 += v1;
        sq = fmaf(v0, v0, sq);
        sq = fmaf(v1, v1, sq);
    }
    g_part[b * HDIM + t] = s0;
    g_part[b * HDIM + t + 256] = s1;
    __shared__ float sh[256];
    sh[t] = sq;
    __syncthreads();
    for (int off = 128; off > 0; off >>= 1) {
        if (t < off) sh[t] += sh[t + off];
        __syncthreads();
    }
    if (t == 0) g_partsq[b] = sh[0];
}

__global__ __launch_bounds__(512) void colfinal() {
    int t = threadIdx.x;   // 512
    float s = 0.0f;
    for (int p = 0; p < 128; p++) s += g_part[p * HDIM + t];
    float mu = s * (1.0f / (float)NROWS);
    g_mu[t] = mu;
    __shared__ float sh[512];
    __shared__ float s_mumu;
    sh[t] = mu * mu;
    __syncthreads();
    for (int off = 256; off > 0; off >>= 1) {
        if (t < off) sh[t] += sh[t + off];
        __syncthreads();
    }
    if (t == 0) s_mumu = sh[0];
    __syncthreads();
    sh[t] = (t < 128) ? g_partsq[t] : 0.0f;
    __syncthreads();
    for (int off = 256; off > 0; off >>= 1) {
        if (t < off) sh[t] += sh[t + off];
        __syncthreads();
    }
    if (t == 0) {
        float var = sh[0] * (1.0f / (float)NROWS) - s_mumu;
        g_invrnm = rsqrtf(1e-6f + var);
    }
}

__global__ void norm_relu(const float* __restrict__ in, float* __restrict__ out) {
    float inv = g_invrnm;
    int total = NROWS * HDIM;
    for (int i = blockIdx.x * blockDim.x + threadIdx.x; i < total; i += gridDim.x * blockDim.x) {
        float v = (in[i] - g_mu[i & (HDIM - 1)]) * inv;
        out[i] = v > 0.0f ? v : 0.0f;
    }
}

// ---------------- launch ----------------
extern "C" void kernel_launch(void* const* d_in, const int* in_sizes, int n_in,
                              void* d_out, int out_size) {
    const float* x   = (const float*)d_in[0];
    const float* adj = (const float*)d_in[1];
    const float* W0  = (const float*)d_in[2];
    const float* W1  = (const float*)d_in[3];
    const float* W2  = (const float*)d_in[4];
    const float* S0  = (const float*)d_in[5];
    const float* S1  = (const float*)d_in[6];
    const float* S2  = (const float*)d_in[7];
    float* out = (float*)d_out;

    float *W0m, *W1m, *W2m, *h0, *h1, *h2, *hC;
    cudaGetSymbolAddress((void**)&W0m, g_W0m);
    cudaGetSymbolAddress((void**)&W1m, g_W1m);
    cudaGetSymbolAddress((void**)&W2m, g_W2m);
    cudaGetSymbolAddress((void**)&h0,  g_h0);
    cudaGetSymbolAddress((void**)&h1,  g_h1);
    cudaGetSymbolAddress((void**)&h2,  g_h2);
    cudaGetSymbolAddress((void**)&hC,  g_hC);

    // adjacency -> CSR + degrees (the mandatory 256MB read)
    build_csr<<<NROWS, 256>>>(adj);

    // exact global threshold (2-level radix select)
    clear_hist<<<64, 1024>>>();
    hist1_k<<<272, 1024>>>(S0, S1, S2);
    find_bin<<<1, 1024>>>();
    hist2_k<<<272, 1024>>>(S0, S1, S2);
    find_thr<<<1, 1024>>>();

    // masked weights
    mask_k<<<256, 1024>>>(W0, S0, W0m, NS0);
    mask_k<<<256, 1024>>>(W1, S1, W1m, NS1);
    mask_k<<<32,  1024>>>(W2, S2, W2m, NS2);

    // layer 0: h0 = x @ W0m^T   [8192,512]
    sgemm_nt<128, 128, 16, 8, 8><<<dim3(FDIM / 128, NROWS / 128), 256>>>(x, W0m, h0, NROWS, HDIM, FDIM);
    // layer 1: h1 = h0 @ W1m^T  [8192,512]
    sgemm_nt<128, 128, 16, 8, 8><<<dim3(HDIM / 128, NROWS / 128), 256>>>(h0, W1m, h1, NROWS, HDIM, HDIM);
    // aggregation: h2 = adj_n @ h1
    spmm512<<<NROWS, 256>>>(h1, h2);
    // pair_norm + relu -> h0 (reuse)
    colstats<<<128, 256>>>(h2);
    colfinal<<<1, 512>>>();
    norm_relu<<<4096, 256>>>(h2, h0);
    // layer 2: hC = h0 @ W2m^T  [8192,64]
    sgemm_nt<128, 64, 16, 8, 4><<<dim3(CDIM / 64, NROWS / 128), 256>>>(h0, W2m, hC, NROWS, CDIM, HDIM);
    // final aggregation into output
    spmm64<<<NROWS, 64>>>(hC, out);
}

// round 12
// speedup vs baseline: 1.0032x; 1.0032x over previous
#include <cuda_runtime.h>
#include <cuda_bf16.h>
#include <mma.h>
#include <cstdint>

using namespace nvcuda;

#define NROWS 8192
#define FDIM  512
#define HDIM  512
#define CDIM  64
#define MAXNZ 128
#define KRANK 278529u   // 1 + round(0.5*(557056-1)), banker's rounding
#define NS0   262144
#define NS1   262144
#define NS2   32768
#define NSTOT 557056

// ---------------- device scratch ----------------
__device__ float g_W0m[HDIM*FDIM];
__device__ float g_W1m[HDIM*HDIM];
__device__ float g_W2m[CDIM*HDIM];
__device__ float g_h0[(size_t)NROWS*HDIM];
__device__ float g_h1[(size_t)NROWS*HDIM];
__device__ float g_h2[(size_t)NROWS*HDIM];
__device__ float g_hC[(size_t)NROWS*CDIM];
__device__ int   g_cols[NROWS*MAXNZ];
__device__ int   g_cnt[NROWS];
__device__ float g_dinv[NROWS];
__device__ unsigned g_hist1[32768];   // zero at load; find_bin re-clears after use
__device__ unsigned g_hist2[65536];   // zero at load; find_thr re-clears after use
__device__ unsigned g_selbin;
__device__ unsigned g_rank2;
__device__ float g_thr;
__device__ float g_part[128*HDIM];
__device__ float g_partsq[128];
__device__ float g_mu[HDIM];
__device__ float g_invrnm;

// ---------------- CSR build ----------------
__global__ __launch_bounds__(256) void build_csr(const float* __restrict__ adj) {
    int r = blockIdx.x;
    int t = threadIdx.x;
    const float4* row4 = (const float4*)(adj + (size_t)r * NROWS);
    int cnt = 0;
    #pragma unroll
    for (int q = 0; q < 8; q++) {
        int i4 = q * 256 + t;
        float4 v = row4[i4];
        int c0 = i4 * 4;
        cnt += (v.x != 0.0f || c0 + 0 == r);
        cnt += (v.y != 0.0f || c0 + 1 == r);
        cnt += (v.z != 0.0f || c0 + 2 == r);
        cnt += (v.w != 0.0f || c0 + 3 == r);
    }
    __shared__ int s[256];
    s[t] = cnt;
    __syncthreads();
    for (int off = 1; off < 256; off <<= 1) {
        int v = (t >= off) ? s[t - off] : 0;
        __syncthreads();
        s[t] += v;
        __syncthreads();
    }
    int excl = s[t] - cnt;
    int total = s[255];
    int w = excl;
    #pragma unroll
    for (int q = 0; q < 8; q++) {
        int i4 = q * 256 + t;
        float4 v = row4[i4];
        int c0 = i4 * 4;
        if ((v.x != 0.0f || c0 + 0 == r) && w < MAXNZ) g_cols[r * MAXNZ + w++] = c0 + 0;
        if ((v.y != 0.0f || c0 + 1 == r) && w < MAXNZ) g_cols[r * MAXNZ + w++] = c0 + 1;
        if ((v.z != 0.0f || c0 + 2 == r) && w < MAXNZ) g_cols[r * MAXNZ + w++] = c0 + 2;
        if ((v.w != 0.0f || c0 + 3 == r) && w < MAXNZ) g_cols[r * MAXNZ + w++] = c0 + 3;
    }
    if (t == 0) {
        g_cnt[r]  = (total < MAXNZ) ? total : MAXNZ;
        g_dinv[r] = rsqrtf((float)total);
    }
}

// ---------------- exact radix-select threshold (self-cleaning, 4 launches) ----------------
__device__ __forceinline__ float pick_score(const float* S0, const float* S1, const float* S2, int i) {
    if (i < NS0) return S0[i];
    if (i < NS0 + NS1) return S1[i - NS0];
    return S2[i - NS0 - NS1];
}

__global__ void hist1_k(const float* __restrict__ S0, const float* __restrict__ S1, const float* __restrict__ S2) {
    for (int i = blockIdx.x * blockDim.x + threadIdx.x; i < NSTOT; i += gridDim.x * blockDim.x) {
        unsigned bits = __float_as_uint(fabsf(pick_score(S0, S1, S2, i)));
        atomicAdd(&g_hist1[bits >> 16], 1u);
    }
}

__global__ __launch_bounds__(1024) void find_bin() {
    int t = threadIdx.x;
    unsigned loc[32];
    unsigned s = 0;
    #pragma unroll
    for (int i = 0; i < 32; i++) { loc[i] = g_hist1[t * 32 + i]; s += loc[i]; }
    __shared__ unsigned sh[1024];
    sh[t] = s;
    __syncthreads();
    for (int off = 1; off < 1024; off <<= 1) {
        unsigned v = (t >= off) ? sh[t - off] : 0u;
        __syncthreads();
        sh[t] += v;
        __syncthreads();
    }
    unsigned incl = sh[t], excl = incl - s;
    if (excl < KRANK && incl >= KRANK) {
        unsigned cum = excl;
        #pragma unroll
        for (int i = 0; i < 32; i++) {
            unsigned c = loc[i];
            if (cum + c >= KRANK) { g_selbin = (unsigned)(t * 32 + i); g_rank2 = KRANK - cum; break; }
            cum += c;
        }
    }
    // self-clean for next graph replay (all reads done above)
    #pragma unroll
    for (int i = 0; i < 32; i++) g_hist1[t * 32 + i] = 0u;
}

__global__ void hist2_k(const float* __restrict__ S0, const float* __restrict__ S1, const float* __restrict__ S2) {
    unsigned bin = g_selbin;
    for (int i = blockIdx.x * blockDim.x + threadIdx.x; i < NSTOT; i += gridDim.x * blockDim.x) {
        unsigned bits = __float_as_uint(fabsf(pick_score(S0, S1, S2, i)));
        if ((bits >> 16) == bin) atomicAdd(&g_hist2[bits & 0xFFFFu], 1u);
    }
}

__global__ __launch_bounds__(1024) void find_thr() {
    int t = threadIdx.x;
    unsigned target = g_rank2, bin = g_selbin;
    unsigned loc[64];
    unsigned s = 0;
    #pragma unroll
    for (int i = 0; i < 64; i++) { loc[i] = g_hist2[t * 64 + i]; s += loc[i]; }
    __shared__ unsigned sh[1024];
    sh[t] = s;
    __syncthreads();
    for (int off = 1; off < 1024; off <<= 1) {
        unsigned v = (t >= off) ? sh[t - off] : 0u;
        __syncthreads();
        sh[t] += v;
        __syncthreads();
    }
    unsigned incl = sh[t], excl = incl - s;
    if (excl < target && incl >= target) {
        unsigned cum = excl;
        #pragma unroll
        for (int i = 0; i < 64; i++) {
            unsigned c = loc[i];
            if (cum + c >= target) {
                g_thr = __uint_as_float((bin << 16) | (unsigned)(t * 64 + i));
                break;
            }
            cum += c;
        }
    }
    // self-clean for next graph replay
    #pragma unroll
    for (int i = 0; i < 64; i++) g_hist2[t * 64 + i] = 0u;
}

// ---------------- masked weights: one launch over [S0|S1|S2] ----------------
__global__ void mask_all(const float* __restrict__ W0, const float* __restrict__ S0,
                         const float* __restrict__ W1, const float* __restrict__ S1,
                         const float* __restrict__ W2, const float* __restrict__ S2,
                         float* __restrict__ W0m, float* __restrict__ W1m, float* __restrict__ W2m) {
    float thr = g_thr;
    for (int i = blockIdx.x * blockDim.x + threadIdx.x; i < NSTOT; i += gridDim.x * blockDim.x) {
        if (i < NS0) {
            W0m[i] = (fabsf(S0[i]) > thr) ? W0[i] : 0.0f;
        } else if (i < NS0 + NS1) {
            int j = i - NS0;
            W1m[j] = (fabsf(S1[j]) > thr) ? W1[j] : 0.0f;
        } else {
            int j = i - NS0 - NS1;
            W2m[j] = (fabsf(S2[j]) > thr) ? W2[j] : 0.0f;
        }
    }
}

// =============== WMMA bf16-split GEMM: C[M,512] = A[M,512] @ W[512,512]^T ===============
// tcgen05 is unusable (harness lowers via compute_103 PTX, no 'a' target), so use the
// baseline-PTX tensor path: wmma m16n16k16 bf16 (HMMA). Hi/lo split:
// C ~= Ahi*Whi^T + Ahi*Wlo^T + Alo*Whi^T, fp32 accumulate.
#define WB_BM 128
#define WB_BN 64
#define WB_BK 64
#define WB_LD (WB_BK + 8)   // 72 bf16 (+16B pad vs bank conflicts)
// dyn smem: (128+128+64+64)*72*2 = 55296 B
#define WB_AHI 0
#define WB_ALO (WB_BM * WB_LD)
#define WB_WHI (2 * WB_BM * WB_LD)
#define WB_WLO (2 * WB_BM * WB_LD + WB_BN * WB_LD)
#define WB_SMEM_ELEMS (2 * WB_BM * WB_LD + 2 * WB_BN * WB_LD)
#define WB_SMEM_BYTES (WB_SMEM_ELEMS * 2)

__device__ __forceinline__ void split_store4(__nv_bfloat16* hi, __nv_bfloat16* lo, float4 v) {
    __nv_bfloat16 h0 = __float2bfloat16(v.x), h1 = __float2bfloat16(v.y);
    __nv_bfloat16 h2 = __float2bfloat16(v.z), h3 = __float2bfloat16(v.w);
    *(__nv_bfloat162*)(hi)     = __nv_bfloat162(h0, h1);
    *(__nv_bfloat162*)(hi + 2) = __nv_bfloat162(h2, h3);
    *(__nv_bfloat162*)(lo)     = __nv_bfloat162(__float2bfloat16(v.x - __bfloat162float(h0)),
                                                __float2bfloat16(v.y - __bfloat162float(h1)));
    *(__nv_bfloat162*)(lo + 2) = __nv_bfloat162(__float2bfloat16(v.z - __bfloat162float(h2)),
                                                __float2bfloat16(v.w - __bfloat162float(h3)));
}

__global__ __launch_bounds__(256) void gemm_wmma_split(const float* __restrict__ A,
                                                       const float* __restrict__ W,
                                                       float* __restrict__ C) {
    extern __shared__ __nv_bfloat16 sm[];
    const int tid = threadIdx.x;
    const int wid = tid >> 5;
    const int rowbase = blockIdx.y * WB_BM;
    const int nbase   = blockIdx.x * WB_BN;
    const int wm = wid & 3;   // 4 warp rows: 32 M-rows each
    const int wn = wid >> 2;  // 2 warp cols: 32 N-cols each

    wmma::fragment<wmma::accumulator, 16, 16, 16, float> acc[2][2];
    #pragma unroll
    for (int i = 0; i < 2; i++)
        #pragma unroll
        for (int j = 0; j < 2; j++) wmma::fill_fragment(acc[i][j], 0.0f);

    const int ar = tid >> 1;          // A row 0..127
    const int ah = tid & 1;           // A col half (32 floats)
    const int wr = tid >> 2;          // W row 0..63
    const int wq = tid & 3;           // W col quarter (16 floats)

    for (int ch = 0; ch < 512 / WB_BK; ch++) {
        const int kbase = ch * WB_BK;
        // load + split A chunk [128 x 64]
        {
            const float* ap = A + (size_t)(rowbase + ar) * 512 + kbase + ah * 32;
            __nv_bfloat16* hi = sm + WB_AHI + ar * WB_LD + ah * 32;
            __nv_bfloat16* lo = sm + WB_ALO + ar * WB_LD + ah * 32;
            #pragma unroll
            for (int q = 0; q < 8; q++)
                split_store4(hi + q * 4, lo + q * 4, *(const float4*)(ap + q * 4));
        }
        // load + split W chunk [64 x 64]
        {
            const float* wp = W + (size_t)(nbase + wr) * 512 + kbase + wq * 16;
            __nv_bfloat16* hi = sm + WB_WHI + wr * WB_LD + wq * 16;
            __nv_bfloat16* lo = sm + WB_WLO + wr * WB_LD + wq * 16;
            #pragma unroll
            for (int q = 0; q < 4; q++)
                split_store4(hi + q * 4, lo + q * 4, *(const float4*)(wp + q * 4));
        }
        __syncthreads();

        #pragma unroll
        for (int term = 0; term < 3; term++) {
            const __nv_bfloat16* aB = sm + ((term == 2) ? WB_ALO : WB_AHI);
            const __nv_bfloat16* bB = sm + ((term == 1) ? WB_WLO : WB_WHI);
            #pragma unroll
            for (int kk = 0; kk < WB_BK / 16; kk++) {
                wmma::fragment<wmma::matrix_a, 16, 16, 16, __nv_bfloat16, wmma::row_major> af[2];
                wmma::fragment<wmma::matrix_b, 16, 16, 16, __nv_bfloat16, wmma::col_major> bf[2];
                #pragma unroll
                for (int i = 0; i < 2; i++)
                    wmma::load_matrix_sync(af[i], aB + (wm * 32 + i * 16) * WB_LD + kk * 16, WB_LD);
                #pragma unroll
                for (int j = 0; j < 2; j++)
                    wmma::load_matrix_sync(bf[j], bB + (wn * 32 + j * 16) * WB_LD + kk * 16, WB_LD);
                #pragma unroll
                for (int i = 0; i < 2; i++)
                    #pragma unroll
                    for (int j = 0; j < 2; j++)
                        wmma::mma_sync(acc[i][j], af[i], bf[j], acc[i][j]);
            }
        }
        __syncthreads();
    }

    #pragma unroll
    for (int i = 0; i < 2; i++)
        #pragma unroll
        for (int j = 0; j < 2; j++)
            wmma::store_matrix_sync(
                C + (size_t)(rowbase + wm * 32 + i * 16) * 512 + nbase + wn * 32 + j * 16,
                acc[i][j], 512, wmma::mem_row_major);
}

// ---------------- SGEMM (fp32) for the small final layer ----------------
template<int BM, int BN, int BK, int TM, int TN>
__global__ __launch_bounds__(256) void sgemm_nt(const float* __restrict__ A,
                                                const float* __restrict__ B,
                                                float* __restrict__ Cmat,
                                                int M, int Nn, int K) {
    __shared__ float As[BK][BM];
    __shared__ float Bs[BK][BN];
    const int tid = threadIdx.x;
    const int brow = blockIdx.y * BM;
    const int bcol = blockIdx.x * BN;
    constexpr int TX = BN / TN;
    const int tx = tid % TX;
    const int ty = tid / TX;

    float acc[TM][TN];
    #pragma unroll
    for (int m = 0; m < TM; m++)
        #pragma unroll
        for (int n = 0; n < TN; n++) acc[m][n] = 0.0f;

    for (int kt = 0; kt < K; kt += BK) {
        #pragma unroll
        for (int i = tid; i < BM * BK / 4; i += 256) {
            int rowi = i / (BK / 4), kq = i % (BK / 4);
            float4 v = *(const float4*)(A + (size_t)(brow + rowi) * K + kt + kq * 4);
            As[kq * 4 + 0][rowi] = v.x; As[kq * 4 + 1][rowi] = v.y;
            As[kq * 4 + 2][rowi] = v.z; As[kq * 4 + 3][rowi] = v.w;
        }
        #pragma unroll
        for (int i = tid; i < BN * BK / 4; i += 256) {
            int rowi = i / (BK / 4), kq = i % (BK / 4);
            float4 v = *(const float4*)(B + (size_t)(bcol + rowi) * K + kt + kq * 4);
            Bs[kq * 4 + 0][rowi] = v.x; Bs[kq * 4 + 1][rowi] = v.y;
            Bs[kq * 4 + 2][rowi] = v.z; Bs[kq * 4 + 3][rowi] = v.w;
        }
        __syncthreads();
        #pragma unroll
        for (int k = 0; k < BK; k++) {
            float a[TM], b[TN];
            #pragma unroll
            for (int m = 0; m < TM; m++) a[m] = As[k][ty * TM + m];
            #pragma unroll
            for (int n = 0; n < TN; n++) b[n] = Bs[k][tx * TN + n];
            #pragma unroll
            for (int m = 0; m < TM; m++)
                #pragma unroll
                for (int n = 0; n < TN; n++) acc[m][n] = fmaf(a[m], b[n], acc[m][n]);
        }
        __syncthreads();
    }
    #pragma unroll
    for (int m = 0; m < TM; m++) {
        float* cp = Cmat + (size_t)(brow + ty * TM + m) * Nn + bcol + tx * TN;
        #pragma unroll
        for (int n = 0; n < TN; n++) cp[n] = acc[m][n];
    }
}

// ---------------- SpMM ----------------
__global__ __launch_bounds__(256) void spmm512(const float* __restrict__ hin, float* __restrict__ hout) {
    int r = blockIdx.x, t = threadIdx.x;
    __shared__ int   sc[MAXNZ];
    __shared__ float sw[MAXNZ];
    int cnt = g_cnt[r];
    for (int i = t; i < cnt; i += 256) {
        int j = g_cols[r * MAXNZ + i];
        sc[i] = j;
        sw[i] = g_dinv[j];
    }
    __syncthreads();
    float a0 = 0.0f, a1 = 0.0f;
    for (int k = 0; k < cnt; k++) {
        const float* hp = hin + (size_t)sc[k] * HDIM;
        float w = sw[k];
        a0 = fmaf(w, hp[t], a0);
        a1 = fmaf(w, hp[t + 256], a1);
    }
    float di = g_dinv[r];
    hout[(size_t)r * HDIM + t] = di * a0;
    hout[(size_t)r * HDIM + t + 256] = di * a1;
}

__global__ __launch_bounds__(64) void spmm64(const float* __restrict__ hin, float* __restrict__ hout) {
    int r = blockIdx.x, t = threadIdx.x;
    __shared__ int   sc[MAXNZ];
    __shared__ float sw[MAXNZ];
    int cnt = g_cnt[r];
    for (int i = t; i < cnt; i += 64) {
        int j = g_cols[r * MAXNZ + i];
        sc[i] = j;
        sw[i] = g_dinv[j];
    }
    __syncthreads();
    float a = 0.0f;
    for (int k = 0; k < cnt; k++)
        a = fmaf(sw[k], hin[(size_t)sc[k] * CDIM + t], a);
    hout[(size_t)r * CDIM + t] = g_dinv[r] * a;
}

// ---------------- PairNorm ----------------
__global__ __launch_bounds__(256) void colstats(const float* __restrict__ h) {
    int b = blockIdx.x, t = threadIdx.x;
    float s0 = 0.0f, s1 = 0.0f, sq = 0.0f;
    for (int r0 = 0; r0 < 64; r0++) {
        size_t r = (size_t)b * 64 + r0;
        float v0 = h[r * HDIM + t];
        float v1 = h[r * HDIM + t + 256];
        s0 += v0; s1 += v1;
        sq = fmaf(v0, v0, sq);
        sq = fmaf(v1, v1, sq);
    }
    g_part[b * HDIM + t] = s0;
    g_part[b * HDIM + t + 256] = s1;
    __shared__ float sh[256];
    sh[t] = sq;
    __syncthreads();
    for (int off = 128; off > 0; off >>= 1) {
        if (t < off) sh[t] += sh[t + off];
        __syncthreads();
    }
    if (t == 0) g_partsq[b] = sh[0];
}

__global__ __launch_bounds__(512) void colfinal() {
    int t = threadIdx.x;
    float s = 0.0f;
    for (int p = 0; p < 128; p++) s += g_part[p * HDIM + t];
    float mu = s * (1.0f / (float)NROWS);
    g_mu[t] = mu;
    __shared__ float sh[512];
    __shared__ float s_mumu;
    sh[t] = mu * mu;
    __syncthreads();
    for (int off = 256; off > 0; off >>= 1) {
        if (t < off) sh[t] += sh[t + off];
        __syncthreads();
    }
    if (t == 0) s_mumu = sh[0];
    __syncthreads();
    sh[t] = (t < 128) ? g_partsq[t] : 0.0f;
    __syncthreads();
    for (int off = 256; off > 0; off >>= 1) {
        if (t < off) sh[t] += sh[t + off];
        __syncthreads();
    }
    if (t == 0) {
        float var = sh[0] * (1.0f / (float)NROWS) - s_mumu;
        g_invrnm = rsqrtf(1e-6f + var);
    }
}

__global__ void norm_relu(const float* __restrict__ in, float* __restrict__ out) {
    float inv = g_invrnm;
    int total = NROWS * HDIM;
    for (int i = blockIdx.x * blockDim.x + threadIdx.x; i < total; i += gridDim.x * blockDim.x) {
        float v = (in[i] - g_mu[i & (HDIM - 1)]) * inv;
        out[i] = v > 0.0f ? v : 0.0f;
    }
}

// ---------------- launch ----------------
extern "C" void kernel_launch(void* const* d_in, const int* in_sizes, int n_in,
                              void* d_out, int out_size) {
    const float* x   = (const float*)d_in[0];
    const float* adj = (const float*)d_in[1];
    const float* W0  = (const float*)d_in[2];
    const float* W1  = (const float*)d_in[3];
    const float* W2  = (const float*)d_in[4];
    const float* S0  = (const float*)d_in[5];
    const float* S1  = (const float*)d_in[6];
    const float* S2  = (const float*)d_in[7];
    float* out = (float*)d_out;

    float *W0m, *W1m, *W2m, *h0, *h1, *h2, *hC;
    cudaGetSymbolAddress((void**)&W0m, g_W0m);
    cudaGetSymbolAddress((void**)&W1m, g_W1m);
    cudaGetSymbolAddress((void**)&W2m, g_W2m);
    cudaGetSymbolAddress((void**)&h0,  g_h0);
    cudaGetSymbolAddress((void**)&h1,  g_h1);
    cudaGetSymbolAddress((void**)&h2,  g_h2);
    cudaGetSymbolAddress((void**)&hC,  g_hC);

    cudaFuncSetAttribute(gemm_wmma_split, cudaFuncAttributeMaxDynamicSharedMemorySize, WB_SMEM_BYTES);

    // adjacency -> CSR + degrees (the mandatory 256MB read)
    build_csr<<<NROWS, 256>>>(adj);

    // exact global threshold (self-cleaning 2-level radix select, 4 launches)
    hist1_k<<<272, 1024>>>(S0, S1, S2);
    find_bin<<<1, 1024>>>();
    hist2_k<<<272, 1024>>>(S0, S1, S2);
    find_thr<<<1, 1024>>>();

    // masked weights (single launch over all three score tensors)
    mask_all<<<272, 1024>>>(W0, S0, W1, S1, W2, S2, W0m, W1m, W2m);

    // layer 0: h0 = x @ W0m^T   (wmma bf16-split)
    gemm_wmma_split<<<dim3(HDIM / WB_BN, NROWS / WB_BM), 256, WB_SMEM_BYTES>>>(x, W0m, h0);
    // layer 1: h1 = h0 @ W1m^T  (wmma bf16-split)
    gemm_wmma_split<<<dim3(HDIM / WB_BN, NROWS / WB_BM), 256, WB_SMEM_BYTES>>>(h0, W1m, h1);
    // aggregation: h2 = adj_n @ h1
    spmm512<<<NROWS, 256>>>(h1, h2);
    // pair_norm + relu -> h0 (reuse)
    colstats<<<128, 256>>>(h2);
    colfinal<<<1, 512>>>();
    norm_relu<<<4096, 256>>>(h2, h0);
    // layer 2: hC = h0 @ W2m^T  [8192,64] (fp32)
    sgemm_nt<128, 64, 16, 8, 4><<<dim3(CDIM / 64, NROWS / 128), 256>>>(h0, W2m, hC, NROWS, CDIM, HDIM);
    // final aggregation into output
    spmm64<<<NROWS, 64>>>(hC, out);
}

// round 15
// speedup vs baseline: 1.2960x; 1.2918x over previous
#include <cuda_runtime.h>
#include <cuda_bf16.h>
#include <mma.h>
#include <cstdint>

using namespace nvcuda;

#define NROWS 8192
#define FDIM  512
#define HDIM  512
#define CDIM  64
#define MAXNZ 128
#define KRANK 278529u   // 1 + round(0.5*(557056-1)), banker's rounding
#define NS0   262144
#define NS1   262144
#define NS2   32768
#define NSTOT 557056

// ---------------- device scratch ----------------
__device__ float g_W2m[CDIM*HDIM];
__device__ __nv_bfloat16 g_W0hi[HDIM*FDIM];
__device__ __nv_bfloat16 g_W0lo[HDIM*FDIM];
__device__ __nv_bfloat16 g_W1hi[HDIM*HDIM];
__device__ __nv_bfloat16 g_W1lo[HDIM*HDIM];
__device__ __nv_bfloat16 g_xhi[(size_t)NROWS*FDIM];
__device__ __nv_bfloat16 g_xlo[(size_t)NROWS*FDIM];
__device__ __nv_bfloat16 g_h0hi[(size_t)NROWS*HDIM];
__device__ __nv_bfloat16 g_h0lo[(size_t)NROWS*HDIM];
__device__ float g_h0[(size_t)NROWS*HDIM];
__device__ float g_h1[(size_t)NROWS*HDIM];
__device__ float g_h2[(size_t)NROWS*HDIM];
__device__ float g_hC[(size_t)NROWS*CDIM];
__device__ int   g_cols[NROWS*MAXNZ];
__device__ int   g_cnt[NROWS];
__device__ float g_dinv[NROWS];
__device__ unsigned g_hist1[32768];   // zero at load; find_bin re-clears after use
__device__ unsigned g_hist2[65536];   // zero at load; find_thr re-clears after use
__device__ unsigned g_selbin;
__device__ unsigned g_rank2;
__device__ float g_thr;
__device__ float g_part[128*HDIM];
__device__ float g_partsq[128];
__device__ float g_mu[HDIM];
__device__ float g_invrnm;

// ---------------- cp.async helpers (sm_80 baseline PTX) ----------------
__device__ __forceinline__ uint32_t smem_u32(const void* p) {
    uint32_t a;
    asm("{ .reg .u64 t; cvta.to.shared.u64 t, %1; cvt.u32.u64 %0, t; }" : "=r"(a) : "l"(p));
    return a;
}
#define CP_ASYNC16(dst, src) asm volatile("cp.async.cg.shared.global [%0], [%1], 16;" :: "r"(dst), "l"(src))
#define CP_COMMIT()          asm volatile("cp.async.commit_group;")
#define CP_WAIT1()           asm volatile("cp.async.wait_group 1;")
#define CP_WAIT0()           asm volatile("cp.async.wait_group 0;")

// ---------------- CSR build: single pass, nonzero mask in registers ----------------
__global__ __launch_bounds__(256) void build_csr(const float* __restrict__ adj) {
    int r = blockIdx.x;
    int t = threadIdx.x;
    const float4* row4 = (const float4*)(adj + (size_t)r * NROWS);
    unsigned mask = 0;
    #pragma unroll
    for (int q = 0; q < 8; q++) {
        int i4 = q * 256 + t;
        float4 v = row4[i4];
        int c0 = i4 * 4;
        if (v.x != 0.0f || c0 + 0 == r) mask |= 1u << (q * 4 + 0);
        if (v.y != 0.0f || c0 + 1 == r) mask |= 1u << (q * 4 + 1);
        if (v.z != 0.0f || c0 + 2 == r) mask |= 1u << (q * 4 + 2);
        if (v.w != 0.0f || c0 + 3 == r) mask |= 1u << (q * 4 + 3);
    }
    int cnt = __popc(mask);
    __shared__ int s[256];
    s[t] = cnt;
    __syncthreads();
    for (int off = 1; off < 256; off <<= 1) {
        int v = (t >= off) ? s[t - off] : 0;
        __syncthreads();
        s[t] += v;
        __syncthreads();
    }
    int excl = s[t] - cnt;
    int total = s[255];
    int w = excl;
    #pragma unroll
    for (int q = 0; q < 8; q++) {
        int c0 = (q * 256 + t) * 4;
        #pragma unroll
        for (int b = 0; b < 4; b++) {
            if ((mask & (1u << (q * 4 + b))) && w < MAXNZ) g_cols[r * MAXNZ + w++] = c0 + b;
        }
    }
    if (t == 0) {
        g_cnt[r]  = (total < MAXNZ) ? total : MAXNZ;
        g_dinv[r] = rsqrtf((float)total);
    }
}

// ---------------- exact radix-select threshold (self-cleaning, 4 launches) ----------------
__device__ __forceinline__ float pick_score(const float* S0, const float* S1, const float* S2, int i) {
    if (i < NS0) return S0[i];
    if (i < NS0 + NS1) return S1[i - NS0];
    return S2[i - NS0 - NS1];
}

__global__ void hist1_k(const float* __restrict__ S0, const float* __restrict__ S1, const float* __restrict__ S2) {
    for (int i = blockIdx.x * blockDim.x + threadIdx.x; i < NSTOT; i += gridDim.x * blockDim.x) {
        unsigned bits = __float_as_uint(fabsf(pick_score(S0, S1, S2, i)));
        atomicAdd(&g_hist1[bits >> 16], 1u);
    }
}

__global__ __launch_bounds__(1024) void find_bin() {
    int t = threadIdx.x;
    unsigned loc[32];
    const uint4* hp = (const uint4*)&g_hist1[t * 32];
    #pragma unroll
    for (int i = 0; i < 8; i++) {
        uint4 v = hp[i];
        loc[i * 4 + 0] = v.x; loc[i * 4 + 1] = v.y; loc[i * 4 + 2] = v.z; loc[i * 4 + 3] = v.w;
    }
    unsigned s = 0;
    #pragma unroll
    for (int i = 0; i < 32; i++) s += loc[i];
    __shared__ unsigned sh[1024];
    sh[t] = s;
    __syncthreads();
    for (int off = 1; off < 1024; off <<= 1) {
        unsigned v = (t >= off) ? sh[t - off] : 0u;
        __syncthreads();
        sh[t] += v;
        __syncthreads();
    }
    unsigned incl = sh[t], excl = incl - s;
    if (excl < KRANK && incl >= KRANK) {
        unsigned cum = excl;
        #pragma unroll
        for (int i = 0; i < 32; i++) {
            unsigned c = loc[i];
            if (cum + c >= KRANK) { g_selbin = (unsigned)(t * 32 + i); g_rank2 = KRANK - cum; break; }
            cum += c;
        }
    }
    uint4 z = make_uint4(0u, 0u, 0u, 0u);
    uint4* hz = (uint4*)&g_hist1[t * 32];
    #pragma unroll
    for (int i = 0; i < 8; i++) hz[i] = z;
}

__global__ void hist2_k(const float* __restrict__ S0, const float* __restrict__ S1, const float* __restrict__ S2) {
    unsigned bin = g_selbin;
    for (int i = blockIdx.x * blockDim.x + threadIdx.x; i < NSTOT; i += gridDim.x * blockDim.x) {
        unsigned bits = __float_as_uint(fabsf(pick_score(S0, S1, S2, i)));
        if ((bits >> 16) == bin) atomicAdd(&g_hist2[bits & 0xFFFFu], 1u);
    }
}

__global__ __launch_bounds__(1024) void find_thr() {
    int t = threadIdx.x;
    unsigned target = g_rank2, bin = g_selbin;
    unsigned loc[64];
    const uint4* hp = (const uint4*)&g_hist2[t * 64];
    #pragma unroll
    for (int i = 0; i < 16; i++) {
        uint4 v = hp[i];
        loc[i * 4 + 0] = v.x; loc[i * 4 + 1] = v.y; loc[i * 4 + 2] = v.z; loc[i * 4 + 3] = v.w;
    }
    unsigned s = 0;
    #pragma unroll
    for (int i = 0; i < 64; i++) s += loc[i];
    __shared__ unsigned sh[1024];
    sh[t] = s;
    __syncthreads();
    for (int off = 1; off < 1024; off <<= 1) {
        unsigned v = (t >= off) ? sh[t - off] : 0u;
        __syncthreads();
        sh[t] += v;
        __syncthreads();
    }
    unsigned incl = sh[t], excl = incl - s;
    if (excl < target && incl >= target) {
        unsigned cum = excl;
        #pragma unroll
        for (int i = 0; i < 64; i++) {
            unsigned c = loc[i];
            if (cum + c >= target) {
                g_thr = __uint_as_float((bin << 16) | (unsigned)(t * 64 + i));
                break;
            }
            cum += c;
        }
    }
    uint4 z = make_uint4(0u, 0u, 0u, 0u);
    uint4* hz = (uint4*)&g_hist2[t * 64];
    #pragma unroll
    for (int i = 0; i < 16; i++) hz[i] = z;
}

// ---------------- split helpers ----------------
__device__ __forceinline__ void split1(float w, __nv_bfloat16* hi, __nv_bfloat16* lo) {
    __nv_bfloat16 h = __float2bfloat16(w);
    *hi = h;
    *lo = __float2bfloat16(w - __bfloat162float(h));
}

// masked weights: one launch; W0/W1 emitted pre-split bf16, W2 fp32
__global__ void mask_all(const float* __restrict__ W0, const float* __restrict__ S0,
                         const float* __restrict__ W1, const float* __restrict__ S1,
                         const float* __restrict__ W2, const float* __restrict__ S2,
                         __nv_bfloat16* __restrict__ W0hi, __nv_bfloat16* __restrict__ W0lo,
                         __nv_bfloat16* __restrict__ W1hi, __nv_bfloat16* __restrict__ W1lo,
                         float* __restrict__ W2m) {
    float thr = g_thr;
    for (int i = blockIdx.x * blockDim.x + threadIdx.x; i < NSTOT; i += gridDim.x * blockDim.x) {
        if (i < NS0) {
            float w = (fabsf(S0[i]) > thr) ? W0[i] : 0.0f;
            split1(w, W0hi + i, W0lo + i);
        } else if (i < NS0 + NS1) {
            int j = i - NS0;
            float w = (fabsf(S1[j]) > thr) ? W1[j] : 0.0f;
            split1(w, W1hi + j, W1lo + j);
        } else {
            int j = i - NS0 - NS1;
            W2m[j] = (fabsf(S2[j]) > thr) ? W2[j] : 0.0f;
        }
    }
}

// fp32 -> (hi,lo) bf16, vectorized
__global__ void splitf(const float* __restrict__ in, __nv_bfloat16* __restrict__ hi,
                       __nv_bfloat16* __restrict__ lo, int n4) {
    for (int i = blockIdx.x * blockDim.x + threadIdx.x; i < n4; i += gridDim.x * blockDim.x) {
        float4 v = ((const float4*)in)[i];
        __nv_bfloat16 h0 = __float2bfloat16(v.x), h1 = __float2bfloat16(v.y);
        __nv_bfloat16 h2 = __float2bfloat16(v.z), h3 = __float2bfloat16(v.w);
        ((__nv_bfloat162*)hi)[i * 2 + 0] = __nv_bfloat162(h0, h1);
        ((__nv_bfloat162*)hi)[i * 2 + 1] = __nv_bfloat162(h2, h3);
        ((__nv_bfloat162*)lo)[i * 2 + 0] = __nv_bfloat162(__float2bfloat16(v.x - __bfloat162float(h0)),
                                                          __float2bfloat16(v.y - __bfloat162float(h1)));
        ((__nv_bfloat162*)lo)[i * 2 + 1] = __nv_bfloat162(__float2bfloat16(v.z - __bfloat162float(h2)),
                                                          __float2bfloat16(v.w - __bfloat162float(h3)));
    }
}

// =============== WMMA bf16-split GEMM, cp.async double-buffered ===============
// C[M,512] = A@W^T with A,W pre-split into (hi,lo) bf16; 3 terms hi*hi + hi*lo + lo*hi.
#define WB_BM 128
#define WB_BN 64
#define WB_BK 64
#define WB_LD (WB_BK + 8)                  // 72 bf16 row stride (144 B, 16B-aligned)
#define ST_AHI 0
#define ST_ALO (WB_BM * WB_LD)             // 9216
#define ST_WHI (2 * WB_BM * WB_LD)         // 18432
#define ST_WLO (2 * WB_BM * WB_LD + WB_BN * WB_LD)  // 23040
#define ST_ELEMS (2 * WB_BM * WB_LD + 2 * WB_BN * WB_LD)  // 27648 elems = 55296 B
#define WB_SMEM_BYTES (2 * ST_ELEMS * 2)   // two stages: 110592 B

__global__ __launch_bounds__(256) void gemm_wmma2(const __nv_bfloat16* __restrict__ Ahi,
                                                  const __nv_bfloat16* __restrict__ Alo,
                                                  const __nv_bfloat16* __restrict__ Whi,
                                                  const __nv_bfloat16* __restrict__ Wlo,
                                                  float* __restrict__ C) {
    extern __shared__ __nv_bfloat16 sm[];
    const int tid = threadIdx.x;
    const int wid = tid >> 5;
    const int rowbase = blockIdx.y * WB_BM;
    const int nbase   = blockIdx.x * WB_BN;
    const int wm = wid & 3;
    const int wn = wid >> 2;

    wmma::fragment<wmma::accumulator, 16, 16, 16, float> acc[2][2];
    #pragma unroll
    for (int i = 0; i < 2; i++)
        #pragma unroll
        for (int j = 0; j < 2; j++) wmma::fill_fragment(acc[i][j], 0.0f);

    const int ar = tid >> 1;   // 0..127
    const int ah = tid & 1;    // 32-elem half
    const int wr = tid >> 2;   // 0..63
    const int wq = tid & 3;    // 16-elem quarter

    const uint32_t smb = smem_u32(sm);
    const uint32_t dA = (uint32_t)(ar * WB_LD + ah * 32) * 2;
    const uint32_t dW = (uint32_t)(wr * WB_LD + wq * 16) * 2;
    const size_t gAoff = (size_t)(rowbase + ar) * 512 + ah * 32;
    const size_t gWoff = (size_t)(nbase + wr) * 512 + wq * 16;

    auto load_stage = [&](int st, int kbase) {
        uint32_t base = smb + (uint32_t)st * (ST_ELEMS * 2);
        const __nv_bfloat16* sa_hi = Ahi + gAoff + kbase;
        const __nv_bfloat16* sa_lo = Alo + gAoff + kbase;
        #pragma unroll
        for (int q = 0; q < 4; q++) {
            CP_ASYNC16(base + ST_AHI * 2 + dA + q * 16, sa_hi + q * 8);
            CP_ASYNC16(base + ST_ALO * 2 + dA + q * 16, sa_lo + q * 8);
        }
        const __nv_bfloat16* sw_hi = Whi + gWoff + kbase;
        const __nv_bfloat16* sw_lo = Wlo + gWoff + kbase;
        #pragma unroll
        for (int q = 0; q < 2; q++) {
            CP_ASYNC16(base + ST_WHI * 2 + dW + q * 16, sw_hi + q * 8);
            CP_ASYNC16(base + ST_WLO * 2 + dW + q * 16, sw_lo + q * 8);
        }
    };

    load_stage(0, 0);
    CP_COMMIT();

    for (int ch = 0; ch < 512 / WB_BK; ch++) {
        if (ch < 7) {
            load_stage((ch + 1) & 1, (ch + 1) * WB_BK);
            CP_COMMIT();
            CP_WAIT1();
        } else {
            CP_WAIT0();
        }
        __syncthreads();

        const __nv_bfloat16* stg = sm + (ch & 1) * ST_ELEMS;
        #pragma unroll
        for (int term = 0; term < 3; term++) {
            const __nv_bfloat16* aB = stg + ((term == 2) ? ST_ALO : ST_AHI);
            const __nv_bfloat16* bB = stg + ((term == 1) ? ST_WLO : ST_WHI);
            #pragma unroll
            for (int kk = 0; kk < WB_BK / 16; kk++) {
                wmma::fragment<wmma::matrix_a, 16, 16, 16, __nv_bfloat16, wmma::row_major> af[2];
                wmma::fragment<wmma::matrix_b, 16, 16, 16, __nv_bfloat16, wmma::col_major> bf[2];
                #pragma unroll
                for (int i = 0; i < 2; i++)
                    wmma::load_matrix_sync(af[i], aB + (wm * 32 + i * 16) * WB_LD + kk * 16, WB_LD);
                #pragma unroll
                for (int j = 0; j < 2; j++)
                    wmma::load_matrix_sync(bf[j], bB + (wn * 32 + j * 16) * WB_LD + kk * 16, WB_LD);
                #pragma unroll
                for (int i = 0; i < 2; i++)
                    #pragma unroll
                    for (int j = 0; j < 2; j++)
                        wmma::mma_sync(acc[i][j], af[i], bf[j], acc[i][j]);
            }
        }
        __syncthreads();
    }

    #pragma unroll
    for (int i = 0; i < 2; i++)
        #pragma unroll
        for (int j = 0; j < 2; j++)
            wmma::store_matrix_sync(
                C + (size_t)(rowbase + wm * 32 + i * 16) * 512 + nbase + wn * 32 + j * 16,
                acc[i][j], 512, wmma::mem_row_major);
}

// ---------------- SGEMM (fp32) for the small final layer ----------------
template<int BM, int BN, int BK, int TM, int TN>
__global__ __launch_bounds__(256) void sgemm_nt(const float* __restrict__ A,
                                                const float* __restrict__ B,
                                                float* __restrict__ Cmat,
                                                int M, int Nn, int K) {
    __shared__ float As[BK][BM];
    __shared__ float Bs[BK][BN];
    const int tid = threadIdx.x;
    const int brow = blockIdx.y * BM;
    const int bcol = blockIdx.x * BN;
    constexpr int TX = BN / TN;
    const int tx = tid % TX;
    const int ty = tid / TX;

    float acc[TM][TN];
    #pragma unroll
    for (int m = 0; m < TM; m++)
        #pragma unroll
        for (int n = 0; n < TN; n++) acc[m][n] = 0.0f;

    for (int kt = 0; kt < K; kt += BK) {
        #pragma unroll
        for (int i = tid; i < BM * BK / 4; i += 256) {
            int rowi = i / (BK / 4), kq = i % (BK / 4);
            float4 v = *(const float4*)(A + (size_t)(brow + rowi) * K + kt + kq * 4);
            As[kq * 4 + 0][rowi] = v.x; As[kq * 4 + 1][rowi] = v.y;
            As[kq * 4 + 2][rowi] = v.z; As[kq * 4 + 3][rowi] = v.w;
        }
        #pragma unroll
        for (int i = tid; i < BN * BK / 4; i += 256) {
            int rowi = i / (BK / 4), kq = i % (BK / 4);
            float4 v = *(const float4*)(B + (size_t)(bcol + rowi) * K + kt + kq * 4);
            Bs[kq * 4 + 0][rowi] = v.x; Bs[kq * 4 + 1][rowi] = v.y;
            Bs[kq * 4 + 2][rowi] = v.z; Bs[kq * 4 + 3][rowi] = v.w;
        }
        __syncthreads();
        #pragma unroll
        for (int k = 0; k < BK; k++) {
            float a[TM], b[TN];
            #pragma unroll
            for (int m = 0; m < TM; m++) a[m] = As[k][ty * TM + m];
            #pragma unroll
            for (int n = 0; n < TN; n++) b[n] = Bs[k][tx * TN + n];
            #pragma unroll
            for (int m = 0; m < TM; m++)
                #pragma unroll
                for (int n = 0; n < TN; n++) acc[m][n] = fmaf(a[m], b[n], acc[m][n]);
        }
        __syncthreads();
    }
    #pragma unroll
    for (int m = 0; m < TM; m++) {
        float* cp = Cmat + (size_t)(brow + ty * TM + m) * Nn + bcol + tx * TN;
        #pragma unroll
        for (int n = 0; n < TN; n++) cp[n] = acc[m][n];
    }
}

// ---------------- SpMM ----------------
__global__ __launch_bounds__(256) void spmm512(const float* __restrict__ hin, float* __restrict__ hout) {
    int r = blockIdx.x, t = threadIdx.x;
    __shared__ int   sc[MAXNZ];
    __shared__ float sw[MAXNZ];
    int cnt = g_cnt[r];
    for (int i = t; i < cnt; i += 256) {
        int j = g_cols[r * MAXNZ + i];
        sc[i] = j;
        sw[i] = g_dinv[j];
    }
    __syncthreads();
    float a0 = 0.0f, a1 = 0.0f;
    for (int k = 0; k < cnt; k++) {
        const float* hp = hin + (size_t)sc[k] * HDIM;
        float w = sw[k];
        a0 = fmaf(w, hp[t], a0);
        a1 = fmaf(w, hp[t + 256], a1);
    }
    float di = g_dinv[r];
    hout[(size_t)r * HDIM + t] = di * a0;
    hout[(size_t)r * HDIM + t + 256] = di * a1;
}

__global__ __launch_bounds__(64) void spmm64(const float* __restrict__ hin, float* __restrict__ hout) {
    int r = blockIdx.x, t = threadIdx.x;
    __shared__ int   sc[MAXNZ];
    __shared__ float sw[MAXNZ];
    int cnt = g_cnt[r];
    for (int i = t; i < cnt; i += 64) {
        int j = g_cols[r * MAXNZ + i];
        sc[i] = j;
        sw[i] = g_dinv[j];
    }
    __syncthreads();
    float a = 0.0f;
    for (int k = 0; k < cnt; k++)
        a = fmaf(sw[k], hin[(size_t)sc[k] * CDIM + t], a);
    hout[(size_t)r * CDIM + t] = g_dinv[r] * a;
}

// ---------------- PairNorm ----------------
__global__ __launch_bounds__(256) void colstats(const float* __restrict__ h) {
    int b = blockIdx.x, t = threadIdx.x;
    float s0 = 0.0f, s1 = 0.0f, sq = 0.0f;
    for (int r0 = 0; r0 < 64; r0++) {
        size_t r = (size_t)b * 64 + r0;
        float v0 = h[r * HDIM + t];
        float v1 = h[r * HDIM + t + 256];
        s0 += v0; s1 += v1;
        sq = fmaf(v0, v0, sq);
        sq = fmaf(v1, v1, sq);
    }
    g_part[b * HDIM + t] = s0;
    g_part[b * HDIM + t + 256] = s1;
    __shared__ float sh[256];
    sh[t] = sq;
    __syncthreads();
    for (int off = 128; off > 0; off >>= 1) {
        if (t < off) sh[t] += sh[t + off];
        __syncthreads();
    }
    if (t == 0) g_partsq[b] = sh[0];
}

__global__ __launch_bounds__(512) void colfinal() {
    int t = threadIdx.x;
    float s = 0.0f;
    for (int p = 0; p < 128; p++) s += g_part[p * HDIM + t];
    float mu = s * (1.0f / (float)NROWS);
    g_mu[t] = mu;
    __shared__ float sh[512];
    __shared__ float s_mumu;
    sh[t] = mu * mu;
    __syncthreads();
    for (int off = 256; off > 0; off >>= 1) {
        if (t < off) sh[t] += sh[t + off];
        __syncthreads();
    }
    if (t == 0) s_mumu = sh[0];
    __syncthreads();
    sh[t] = (t < 128) ? g_partsq[t] : 0.0f;
    __syncthreads();
    for (int off = 256; off > 0; off >>= 1) {
        if (t < off) sh[t] += sh[t + off];
        __syncthreads();
    }
    if (t == 0) {
        float var = sh[0] * (1.0f / (float)NROWS) - s_mumu;
        g_invrnm = rsqrtf(1e-6f + var);
    }
}

__global__ void norm_relu(const float* __restrict__ in, float* __restrict__ out) {
    float inv = g_invrnm;
    int total = NROWS * HDIM;
    for (int i = blockIdx.x * blockDim.x + threadIdx.x; i < total; i += gridDim.x * blockDim.x) {
        float v = (in[i] - g_mu[i & (HDIM - 1)]) * inv;
        out[i] = v > 0.0f ? v : 0.0f;
    }
}

// ---------------- launch ----------------
extern "C" void kernel_launch(void* const* d_in, const int* in_sizes, int n_in,
                              void* d_out, int out_size) {
    const float* x   = (const float*)d_in[0];
    const float* adj = (const float*)d_in[1];
    const float* W0  = (const float*)d_in[2];
    const float* W1  = (const float*)d_in[3];
    const float* W2  = (const float*)d_in[4];
    const float* S0  = (const float*)d_in[5];
    const float* S1  = (const float*)d_in[6];
    const float* S2  = (const float*)d_in[7];
    float* out = (float*)d_out;

    float *W2m, *h0, *h1, *h2, *hC;
    __nv_bfloat16 *W0hi, *W0lo, *W1hi, *W1lo, *xhi, *xlo, *h0hi, *h0lo;
    cudaGetSymbolAddress((void**)&W2m,  g_W2m);
    cudaGetSymbolAddress((void**)&W0hi, g_W0hi);
    cudaGetSymbolAddress((void**)&W0lo, g_W0lo);
    cudaGetSymbolAddress((void**)&W1hi, g_W1hi);
    cudaGetSymbolAddress((void**)&W1lo, g_W1lo);
    cudaGetSymbolAddress((void**)&xhi,  g_xhi);
    cudaGetSymbolAddress((void**)&xlo,  g_xlo);
    cudaGetSymbolAddress((void**)&h0hi, g_h0hi);
    cudaGetSymbolAddress((void**)&h0lo, g_h0lo);
    cudaGetSymbolAddress((void**)&h0,   g_h0);
    cudaGetSymbolAddress((void**)&h1,   g_h1);
    cudaGetSymbolAddress((void**)&h2,   g_h2);
    cudaGetSymbolAddress((void**)&hC,   g_hC);

    cudaFuncSetAttribute(gemm_wmma2, cudaFuncAttributeMaxDynamicSharedMemorySize, WB_SMEM_BYTES);

    // adjacency -> CSR + degrees (single pass over the 256MB)
    build_csr<<<NROWS, 256>>>(adj);

    // pre-split x (independent of threshold)
    splitf<<<272, 1024>>>(x, xhi, xlo, NROWS * FDIM / 4);

    // exact global threshold (self-cleaning 2-level radix select)
    hist1_k<<<272, 1024>>>(S0, S1, S2);
    find_bin<<<1, 1024>>>();
    hist2_k<<<272, 1024>>>(S0, S1, S2);
    find_thr<<<1, 1024>>>();

    // masked weights, pre-split bf16 for W0/W1
    mask_all<<<272, 1024>>>(W0, S0, W1, S1, W2, S2, W0hi, W0lo, W1hi, W1lo, W2m);

    // layer 0: h0 = x @ W0m^T
    gemm_wmma2<<<dim3(HDIM / WB_BN, NROWS / WB_BM), 256, WB_SMEM_BYTES>>>(xhi, xlo, W0hi, W0lo, h0);
    // split h0 for layer 1
    splitf<<<272, 1024>>>(h0, h0hi, h0lo, NROWS * HDIM / 4);
    // layer 1: h1 = h0 @ W1m^T
    gemm_wmma2<<<dim3(HDIM / WB_BN, NROWS / WB_BM), 256, WB_SMEM_BYTES>>>(h0hi, h0lo, W1hi, W1lo, h1);
    // aggregation: h2 = adj_n @ h1
    spmm512<<<NROWS, 256>>>(h1, h2);
    // pair_norm + relu -> h0 (reuse)
    colstats<<<128, 256>>>(h2);
    colfinal<<<1, 512>>>();
    norm_relu<<<4096, 256>>>(h2, h0);
    // layer 2: hC = h0 @ W2m^T  [8192,64] (fp32)
    sgemm_nt<128, 64, 16, 8, 4><<<dim3(CDIM / 64, NROWS / 128), 256>>>(h0, W2m, hC, NROWS, CDIM, HDIM);
    // final aggregation into output
    spmm64<<<NROWS, 64>>>(hC, out);
}

// round 17
// speedup vs baseline: 1.3649x; 1.0532x over previous
#include <cuda_runtime.h>
#include <cuda_bf16.h>
#include <mma.h>
#include <cstdint>

using namespace nvcuda;

#define NROWS 8192
#define FDIM  512
#define HDIM  512
#define CDIM  64
#define MAXNZ 128
#define KRANK 278529u   // 1 + round(0.5*(557056-1)), banker's rounding
#define NS0   262144
#define NS1   262144
#define NS2   32768
#define NSTOT 557056

// ---------------- device scratch ----------------
__device__ float g_W2m[CDIM*HDIM];
__device__ __nv_bfloat16 g_W0hi[HDIM*FDIM];
__device__ __nv_bfloat16 g_W0lo[HDIM*FDIM];
__device__ __nv_bfloat16 g_W1hi[HDIM*HDIM];
__device__ __nv_bfloat16 g_W1lo[HDIM*HDIM];
__device__ __nv_bfloat16 g_xhi[(size_t)NROWS*FDIM];
__device__ __nv_bfloat16 g_xlo[(size_t)NROWS*FDIM];
__device__ __nv_bfloat16 g_h0hi[(size_t)NROWS*HDIM];
__device__ __nv_bfloat16 g_h0lo[(size_t)NROWS*HDIM];
__device__ float g_h0[(size_t)NROWS*HDIM];
__device__ float g_h1[(size_t)NROWS*HDIM];
__device__ float g_h2[(size_t)NROWS*HDIM];
__device__ float g_hC[(size_t)NROWS*CDIM];
__device__ int   g_cols[NROWS*MAXNZ];
__device__ int   g_cnt[NROWS];
__device__ float g_dinv[NROWS];
__device__ unsigned g_hist1[32768];   // zero at load; find_bin re-clears after use
__device__ unsigned g_hist2[65536];   // zero at load; find_thr re-clears after use
__device__ unsigned g_selbin;
__device__ unsigned g_rank2;
__device__ float g_thr;
__device__ float g_part[128*HDIM];
__device__ float g_partsq[128];
__device__ float g_mu[HDIM];
__device__ float g_invrnm;

// ---------------- cp.async helpers (sm_80 baseline PTX) ----------------
__device__ __forceinline__ uint32_t smem_u32(const void* p) {
    uint32_t a;
    asm("{ .reg .u64 t; cvta.to.shared.u64 t, %1; cvt.u32.u64 %0, t; }" : "=r"(a) : "l"(p));
    return a;
}
#define CP_ASYNC16(dst, src) asm volatile("cp.async.cg.shared.global [%0], [%1], 16;" :: "r"(dst), "l"(src))
#define CP_COMMIT()          asm volatile("cp.async.commit_group;")
#define CP_WAIT1()           asm volatile("cp.async.wait_group 1;")
#define CP_WAIT0()           asm volatile("cp.async.wait_group 0;")

// ---------------- CSR build: single pass, nonzero mask in registers ----------------
__global__ __launch_bounds__(256) void build_csr(const float* __restrict__ adj) {
    int r = blockIdx.x;
    int t = threadIdx.x;
    const float4* row4 = (const float4*)(adj + (size_t)r * NROWS);
    unsigned mask = 0;
    #pragma unroll
    for (int q = 0; q < 8; q++) {
        int i4 = q * 256 + t;
        float4 v = row4[i4];
        int c0 = i4 * 4;
        if (v.x != 0.0f || c0 + 0 == r) mask |= 1u << (q * 4 + 0);
        if (v.y != 0.0f || c0 + 1 == r) mask |= 1u << (q * 4 + 1);
        if (v.z != 0.0f || c0 + 2 == r) mask |= 1u << (q * 4 + 2);
        if (v.w != 0.0f || c0 + 3 == r) mask |= 1u << (q * 4 + 3);
    }
    int cnt = __popc(mask);
    __shared__ int s[256];
    s[t] = cnt;
    __syncthreads();
    for (int off = 1; off < 256; off <<= 1) {
        int v = (t >= off) ? s[t - off] : 0;
        __syncthreads();
        s[t] += v;
        __syncthreads();
    }
    int excl = s[t] - cnt;
    int total = s[255];
    int w = excl;
    #pragma unroll
    for (int q = 0; q < 8; q++) {
        int c0 = (q * 256 + t) * 4;
        #pragma unroll
        for (int b = 0; b < 4; b++) {
            if ((mask & (1u << (q * 4 + b))) && w < MAXNZ) g_cols[r * MAXNZ + w++] = c0 + b;
        }
    }
    if (t == 0) {
        g_cnt[r]  = (total < MAXNZ) ? total : MAXNZ;
        g_dinv[r] = rsqrtf((float)total);
    }
}

// ---------------- exact radix-select threshold (self-cleaning, 4 launches) ----------------
__device__ __forceinline__ float pick_score(const float* S0, const float* S1, const float* S2, int i) {
    if (i < NS0) return S0[i];
    if (i < NS0 + NS1) return S1[i - NS0];
    return S2[i - NS0 - NS1];
}

__global__ void hist1_k(const float* __restrict__ S0, const float* __restrict__ S1, const float* __restrict__ S2) {
    for (int i = blockIdx.x * blockDim.x + threadIdx.x; i < NSTOT; i += gridDim.x * blockDim.x) {
        unsigned bits = __float_as_uint(fabsf(pick_score(S0, S1, S2, i)));
        atomicAdd(&g_hist1[bits >> 16], 1u);
    }
}

__global__ __launch_bounds__(1024) void find_bin() {
    int t = threadIdx.x;
    unsigned loc[32];
    const uint4* hp = (const uint4*)&g_hist1[t * 32];
    #pragma unroll
    for (int i = 0; i < 8; i++) {
        uint4 v = hp[i];
        loc[i * 4 + 0] = v.x; loc[i * 4 + 1] = v.y; loc[i * 4 + 2] = v.z; loc[i * 4 + 3] = v.w;
    }
    unsigned s = 0;
    #pragma unroll
    for (int i = 0; i < 32; i++) s += loc[i];
    __shared__ unsigned sh[1024];
    sh[t] = s;
    __syncthreads();
    for (int off = 1; off < 1024; off <<= 1) {
        unsigned v = (t >= off) ? sh[t - off] : 0u;
        __syncthreads();
        sh[t] += v;
        __syncthreads();
    }
    unsigned incl = sh[t], excl = incl - s;
    if (excl < KRANK && incl >= KRANK) {
        unsigned cum = excl;
        #pragma unroll
        for (int i = 0; i < 32; i++) {
            unsigned c = loc[i];
            if (cum + c >= KRANK) { g_selbin = (unsigned)(t * 32 + i); g_rank2 = KRANK - cum; break; }
            cum += c;
        }
    }
    uint4 z = make_uint4(0u, 0u, 0u, 0u);
    uint4* hz = (uint4*)&g_hist1[t * 32];
    #pragma unroll
    for (int i = 0; i < 8; i++) hz[i] = z;
}

__global__ void hist2_k(const float* __restrict__ S0, const float* __restrict__ S1, const float* __restrict__ S2) {
    unsigned bin = g_selbin;
    for (int i = blockIdx.x * blockDim.x + threadIdx.x; i < NSTOT; i += gridDim.x * blockDim.x) {
        unsigned bits = __float_as_uint(fabsf(pick_score(S0, S1, S2, i)));
        if ((bits >> 16) == bin) atomicAdd(&g_hist2[bits & 0xFFFFu], 1u);
    }
}

__global__ __launch_bounds__(1024) void find_thr() {
    int t = threadIdx.x;
    unsigned target = g_rank2, bin = g_selbin;
    unsigned loc[64];
    const uint4* hp = (const uint4*)&g_hist2[t * 64];
    #pragma unroll
    for (int i = 0; i < 16; i++) {
        uint4 v = hp[i];
        loc[i * 4 + 0] = v.x; loc[i * 4 + 1] = v.y; loc[i * 4 + 2] = v.z; loc[i * 4 + 3] = v.w;
    }
    unsigned s = 0;
    #pragma unroll
    for (int i = 0; i < 64; i++) s += loc[i];
    __shared__ unsigned sh[1024];
    sh[t] = s;
    __syncthreads();
    for (int off = 1; off < 1024; off <<= 1) {
        unsigned v = (t >= off) ? sh[t - off] : 0u;
        __syncthreads();
        sh[t] += v;
        __syncthreads();
    }
    unsigned incl = sh[t], excl = incl - s;
    if (excl < target && incl >= target) {
        unsigned cum = excl;
        #pragma unroll
        for (int i = 0; i < 64; i++) {
            unsigned c = loc[i];
            if (cum + c >= target) {
                g_thr = __uint_as_float((bin << 16) | (unsigned)(t * 64 + i));
                break;
            }
            cum += c;
        }
    }
    uint4 z = make_uint4(0u, 0u, 0u, 0u);
    uint4* hz = (uint4*)&g_hist2[t * 64];
    #pragma unroll
    for (int i = 0; i < 16; i++) hz[i] = z;
}

// ---------------- split helpers ----------------
__device__ __forceinline__ void split1(float w, __nv_bfloat16* hi, __nv_bfloat16* lo) {
    __nv_bfloat16 h = __float2bfloat16(w);
    *hi = h;
    *lo = __float2bfloat16(w - __bfloat162float(h));
}

// masked weights: one launch; W0/W1 emitted pre-split bf16, W2 fp32
__global__ void mask_all(const float* __restrict__ W0, const float* __restrict__ S0,
                         const float* __restrict__ W1, const float* __restrict__ S1,
                         const float* __restrict__ W2, const float* __restrict__ S2,
                         __nv_bfloat16* __restrict__ W0hi, __nv_bfloat16* __restrict__ W0lo,
                         __nv_bfloat16* __restrict__ W1hi, __nv_bfloat16* __restrict__ W1lo,
                         float* __restrict__ W2m) {
    float thr = g_thr;
    for (int i = blockIdx.x * blockDim.x + threadIdx.x; i < NSTOT; i += gridDim.x * blockDim.x) {
        if (i < NS0) {
            float w = (fabsf(S0[i]) > thr) ? W0[i] : 0.0f;
            split1(w, W0hi + i, W0lo + i);
        } else if (i < NS0 + NS1) {
            int j = i - NS0;
            float w = (fabsf(S1[j]) > thr) ? W1[j] : 0.0f;
            split1(w, W1hi + j, W1lo + j);
        } else {
            int j = i - NS0 - NS1;
            W2m[j] = (fabsf(S2[j]) > thr) ? W2[j] : 0.0f;
        }
    }
}

// fp32 -> (hi,lo) bf16, vectorized (x only now)
__global__ void splitf(const float* __restrict__ in, __nv_bfloat16* __restrict__ hi,
                       __nv_bfloat16* __restrict__ lo, int n4) {
    for (int i = blockIdx.x * blockDim.x + threadIdx.x; i < n4; i += gridDim.x * blockDim.x) {
        float4 v = ((const float4*)in)[i];
        __nv_bfloat16 h0 = __float2bfloat16(v.x), h1 = __float2bfloat16(v.y);
        __nv_bfloat16 h2 = __float2bfloat16(v.z), h3 = __float2bfloat16(v.w);
        ((__nv_bfloat162*)hi)[i * 2 + 0] = __nv_bfloat162(h0, h1);
        ((__nv_bfloat162*)hi)[i * 2 + 1] = __nv_bfloat162(h2, h3);
        ((__nv_bfloat162*)lo)[i * 2 + 0] = __nv_bfloat162(__float2bfloat16(v.x - __bfloat162float(h0)),
                                                          __float2bfloat16(v.y - __bfloat162float(h1)));
        ((__nv_bfloat162*)lo)[i * 2 + 1] = __nv_bfloat162(__float2bfloat16(v.z - __bfloat162float(h2)),
                                                          __float2bfloat16(v.w - __bfloat162float(h3)));
    }
}

// =============== WMMA bf16-split GEMM, cp.async double-buffered, BM=BN=128 ===============
// C[M,512] = A@W^T, A/W pre-split (hi,lo) bf16; 3 terms. OUTMODE 0: fp32 C. 1: bf16 hi/lo C.
#define WB_BM 128
#define WB_BN 128
#define WB_BK 64
#define WB_LD (WB_BK + 8)                  // 72 bf16 row stride (144 B)
#define ST_AHI 0
#define ST_ALO (WB_BM * WB_LD)             // 9216
#define ST_WHI (2 * WB_BM * WB_LD)         // 18432
#define ST_WLO (3 * WB_BM * WB_LD)         // 27648
#define ST_ELEMS (4 * WB_BM * WB_LD)       // 36864 elems = 73728 B
#define WB_SMEM_BYTES (2 * ST_ELEMS * 2)   // two stages: 147456 B

template<int OUTMODE>
__global__ __launch_bounds__(256) void gemm_wmma2(const __nv_bfloat16* __restrict__ Ahi,
                                                  const __nv_bfloat16* __restrict__ Alo,
                                                  const __nv_bfloat16* __restrict__ Whi,
                                                  const __nv_bfloat16* __restrict__ Wlo,
                                                  float* __restrict__ Cf,
                                                  __nv_bfloat16* __restrict__ Chi,
                                                  __nv_bfloat16* __restrict__ Clo) {
    extern __shared__ __nv_bfloat16 sm[];
    const int tid = threadIdx.x;
    const int wid = tid >> 5;
    const int lane = tid & 31;
    const int rowbase = blockIdx.y * WB_BM;
    const int nbase   = blockIdx.x * WB_BN;
    const int wm = wid & 3;   // 4 warp rows x 32 M
    const int wn = wid >> 2;  // 2 warp cols x 64 N

    wmma::fragment<wmma::accumulator, 16, 16, 16, float> acc[2][4];
    #pragma unroll
    for (int i = 0; i < 2; i++)
        #pragma unroll
        for (int j = 0; j < 4; j++) wmma::fill_fragment(acc[i][j], 0.0f);

    const int ar = tid >> 1;   // 0..127
    const int ah = tid & 1;    // 32-elem half

    const uint32_t smb = smem_u32(sm);
    const uint32_t dA = (uint32_t)(ar * WB_LD + ah * 32) * 2;
    const size_t gAoff = (size_t)(rowbase + ar) * 512 + ah * 32;
    const size_t gWoff = (size_t)(nbase + ar) * 512 + ah * 32;

    auto load_stage = [&](int st, int kbase) {
        uint32_t base = smb + (uint32_t)st * (ST_ELEMS * 2);
        const __nv_bfloat16* sa_hi = Ahi + gAoff + kbase;
        const __nv_bfloat16* sa_lo = Alo + gAoff + kbase;
        const __nv_bfloat16* sw_hi = Whi + gWoff + kbase;
        const __nv_bfloat16* sw_lo = Wlo + gWoff + kbase;
        #pragma unroll
        for (int q = 0; q < 4; q++) {
            CP_ASYNC16(base + ST_AHI * 2 + dA + q * 16, sa_hi + q * 8);
            CP_ASYNC16(base + ST_ALO * 2 + dA + q * 16, sa_lo + q * 8);
            CP_ASYNC16(base + ST_WHI * 2 + dA + q * 16, sw_hi + q * 8);
            CP_ASYNC16(base + ST_WLO * 2 + dA + q * 16, sw_lo + q * 8);
        }
    };

    load_stage(0, 0);
    CP_COMMIT();

    for (int ch = 0; ch < 512 / WB_BK; ch++) {
        if (ch < 7) {
            load_stage((ch + 1) & 1, (ch + 1) * WB_BK);
            CP_COMMIT();
            CP_WAIT1();
        } else {
            CP_WAIT0();
        }
        __syncthreads();

        const __nv_bfloat16* stg = sm + (ch & 1) * ST_ELEMS;
        #pragma unroll
        for (int term = 0; term < 3; term++) {
            const __nv_bfloat16* aB = stg + ((term == 2) ? ST_ALO : ST_AHI);
            const __nv_bfloat16* bB = stg + ((term == 1) ? ST_WLO : ST_WHI);
            #pragma unroll
            for (int kk = 0; kk < WB_BK / 16; kk++) {
                wmma::fragment<wmma::matrix_a, 16, 16, 16, __nv_bfloat16, wmma::row_major> af[2];
                wmma::fragment<wmma::matrix_b, 16, 16, 16, __nv_bfloat16, wmma::col_major> bf[4];
                #pragma unroll
                for (int i = 0; i < 2; i++)
                    wmma::load_matrix_sync(af[i], aB + (wm * 32 + i * 16) * WB_LD + kk * 16, WB_LD);
                #pragma unroll
                for (int j = 0; j < 4; j++)
                    wmma::load_matrix_sync(bf[j], bB + (wn * 64 + j * 16) * WB_LD + kk * 16, WB_LD);
                #pragma unroll
                for (int i = 0; i < 2; i++)
                    #pragma unroll
                    for (int j = 0; j < 4; j++)
                        wmma::mma_sync(acc[i][j], af[i], bf[j], acc[i][j]);
            }
        }
        __syncthreads();
    }

    if (OUTMODE == 0) {
        #pragma unroll
        for (int i = 0; i < 2; i++)
            #pragma unroll
            for (int j = 0; j < 4; j++)
                wmma::store_matrix_sync(
                    Cf + (size_t)(rowbase + wm * 32 + i * 16) * 512 + nbase + wn * 64 + j * 16,
                    acc[i][j], 512, wmma::mem_row_major);
    } else {
        // split epilogue: bounce each 16x16 frag through smem, emit hi/lo bf16
        float* patch = (float*)sm + wid * 16 * 20;   // 16x20 fp32 per warp
        const int pr = lane >> 1, ph = lane & 1;
        #pragma unroll
        for (int i = 0; i < 2; i++)
            #pragma unroll
            for (int j = 0; j < 4; j++) {
                wmma::store_matrix_sync(patch, acc[i][j], 20, wmma::mem_row_major);
                __syncwarp();
                float4 v0 = *(float4*)(patch + pr * 20 + ph * 8);
                float4 v1 = *(float4*)(patch + pr * 20 + ph * 8 + 4);
                float vv[8] = {v0.x, v0.y, v0.z, v0.w, v1.x, v1.y, v1.z, v1.w};
                __align__(16) __nv_bfloat162 hh[4];
                __align__(16) __nv_bfloat162 ll[4];
                #pragma unroll
                for (int k = 0; k < 4; k++) {
                    __nv_bfloat16 a = __float2bfloat16(vv[2 * k]);
                    __nv_bfloat16 b = __float2bfloat16(vv[2 * k + 1]);
                    hh[k] = __nv_bfloat162(a, b);
                    ll[k] = __nv_bfloat162(__float2bfloat16(vv[2 * k] - __bfloat162float(a)),
                                           __float2bfloat16(vv[2 * k + 1] - __bfloat162float(b)));
                }
                size_t go = (size_t)(rowbase + wm * 32 + i * 16 + pr) * 512
                          + nbase + wn * 64 + j * 16 + ph * 8;
                *(uint4*)(Chi + go) = *(uint4*)hh;
                *(uint4*)(Clo + go) = *(uint4*)ll;
                __syncwarp();
            }
    }
}

// ---------------- SGEMM (fp32) for the small final layer ----------------
template<int BM, int BN, int BK, int TM, int TN>
__global__ __launch_bounds__(256) void sgemm_nt(const float* __restrict__ A,
                                                const float* __restrict__ B,
                                                float* __restrict__ Cmat,
                                                int M, int Nn, int K) {
    __shared__ float As[BK][BM];
    __shared__ float Bs[BK][BN];
    const int tid = threadIdx.x;
    const int brow = blockIdx.y * BM;
    const int bcol = blockIdx.x * BN;
    constexpr int TX = BN / TN;
    const int tx = tid % TX;
    const int ty = tid / TX;

    float acc[TM][TN];
    #pragma unroll
    for (int m = 0; m < TM; m++)
        #pragma unroll
        for (int n = 0; n < TN; n++) acc[m][n] = 0.0f;

    for (int kt = 0; kt < K; kt += BK) {
        #pragma unroll
        for (int i = tid; i < BM * BK / 4; i += 256) {
            int rowi = i / (BK / 4), kq = i % (BK / 4);
            float4 v = *(const float4*)(A + (size_t)(brow + rowi) * K + kt + kq * 4);
            As[kq * 4 + 0][rowi] = v.x; As[kq * 4 + 1][rowi] = v.y;
            As[kq * 4 + 2][rowi] = v.z; As[kq * 4 + 3][rowi] = v.w;
        }
        #pragma unroll
        for (int i = tid; i < BN * BK / 4; i += 256) {
            int rowi = i / (BK / 4), kq = i % (BK / 4);
            float4 v = *(const float4*)(B + (size_t)(bcol + rowi) * K + kt + kq * 4);
            Bs[kq * 4 + 0][rowi] = v.x; Bs[kq * 4 + 1][rowi] = v.y;
            Bs[kq * 4 + 2][rowi] = v.z; Bs[kq * 4 + 3][rowi] = v.w;
        }
        __syncthreads();
        #pragma unroll
        for (int k = 0; k < BK; k++) {
            float a[TM], b[TN];
            #pragma unroll
            for (int m = 0; m < TM; m++) a[m] = As[k][ty * TM + m];
            #pragma unroll
            for (int n = 0; n < TN; n++) b[n] = Bs[k][tx * TN + n];
            #pragma unroll
            for (int m = 0; m < TM; m++)
                #pragma unroll
                for (int n = 0; n < TN; n++) acc[m][n] = fmaf(a[m], b[n], acc[m][n]);
        }
        __syncthreads();
    }
    #pragma unroll
    for (int m = 0; m < TM; m++) {
        float* cp = Cmat + (size_t)(brow + ty * TM + m) * Nn + bcol + tx * TN;
        #pragma unroll
        for (int n = 0; n < TN; n++) cp[n] = acc[m][n];
    }
}

// ---------------- SpMM ----------------
__global__ __launch_bounds__(256) void spmm512(const float* __restrict__ hin, float* __restrict__ hout) {
    int r = blockIdx.x, t = threadIdx.x;
    __shared__ int   sc[MAXNZ];
    __shared__ float sw[MAXNZ];
    int cnt = g_cnt[r];
    for (int i = t; i < cnt; i += 256) {
        int j = g_cols[r * MAXNZ + i];
        sc[i] = j;
        sw[i] = g_dinv[j];
    }
    __syncthreads();
    float a0 = 0.0f, a1 = 0.0f;
    for (int k = 0; k < cnt; k++) {
        const float* hp = hin + (size_t)sc[k] * HDIM;
        float w = sw[k];
        a0 = fmaf(w, hp[t], a0);
        a1 = fmaf(w, hp[t + 256], a1);
    }
    float di = g_dinv[r];
    hout[(size_t)r * HDIM + t] = di * a0;
    hout[(size_t)r * HDIM + t + 256] = di * a1;
}

__global__ __launch_bounds__(64) void spmm64(const float* __restrict__ hin, float* __restrict__ hout) {
    int r = blockIdx.x, t = threadIdx.x;
    __shared__ int   sc[MAXNZ];
    __shared__ float sw[MAXNZ];
    int cnt = g_cnt[r];
    for (int i = t; i < cnt; i += 64) {
        int j = g_cols[r * MAXNZ + i];
        sc[i] = j;
        sw[i] = g_dinv[j];
    }
    __syncthreads();
    float a = 0.0f;
    for (int k = 0; k < cnt; k++)
        a = fmaf(sw[k], hin[(size_t)sc[k] * CDIM + t], a);
    hout[(size_t)r * CDIM + t] = g_dinv[r] * a;
}

// ---------------- PairNorm ----------------
__global__ __launch_bounds__(256) void colstats(const float* __restrict__ h) {
    int b = blockIdx.x, t = threadIdx.x;
    float s0 = 0.0f, s1 = 0.0f, sq = 0.0f;
    for (int r0 = 0; r0 < 64; r0++) {
        size_t r = (size_t)b * 64 + r0;
        float v0 = h[r * HDIM + t];
        float v1 = h[r * HDIM + t + 256];
        s0 += v0; s1 += v1;
        sq = fmaf(v0, v0, sq);
        sq = fmaf(v1, v1, sq);
    }
    g_part[b * HDIM + t] = s0;
    g_part[b * HDIM + t + 256] = s1;
    __shared__ float sh[256];
    sh[t] = sq;
    __syncthreads();
    for (int off = 128; off > 0; off >>= 1) {
        if (t < off) sh[t] += sh[t + off];
        __syncthreads();
    }
    if (t == 0) g_partsq[b] = sh[0];
}

__global__ __launch_bounds__(512) void colfinal() {
    int t = threadIdx.x;
    float s = 0.0f;
    for (int p = 0; p < 128; p++) s += g_part[p * HDIM + t];
    float mu = s * (1.0f / (float)NROWS);
    g_mu[t] = mu;
    __shared__ float sh[512];
    __shared__ float s_mumu;
    sh[t] = mu * mu;
    __syncthreads();
    for (int off = 256; off > 0; off >>= 1) {
        if (t < off) sh[t] += sh[t + off];
        __syncthreads();
    }
    if (t == 0) s_mumu = sh[0];
    __syncthreads();
    sh[t] = (t < 128) ? g_partsq[t] : 0.0f;
    __syncthreads();
    for (int off = 256; off > 0; off >>= 1) {
        if (t < off) sh[t] += sh[t + off];
        __syncthreads();
    }
    if (t == 0) {
        float var = sh[0] * (1.0f / (float)NROWS) - s_mumu;
        g_invrnm = rsqrtf(1e-6f + var);
    }
}

__global__ void norm_relu(const float* __restrict__ in, float* __restrict__ out) {
    float inv = g_invrnm;
    int total = NROWS * HDIM;
    for (int i = blockIdx.x * blockDim.x + threadIdx.x; i < total; i += gridDim.x * blockDim.x) {
        float v = (in[i] - g_mu[i & (HDIM - 1)]) * inv;
        out[i] = v > 0.0f ? v : 0.0f;
    }
}

// ---------------- launch ----------------
extern "C" void kernel_launch(void* const* d_in, const int* in_sizes, int n_in,
                              void* d_out, int out_size) {
    const float* x   = (const float*)d_in[0];
    const float* adj = (const float*)d_in[1];
    const float* W0  = (const float*)d_in[2];
    const float* W1  = (const float*)d_in[3];
    const float* W2  = (const float*)d_in[4];
    const float* S0  = (const float*)d_in[5];
    const float* S1  = (const float*)d_in[6];
    const float* S2  = (const float*)d_in[7];
    float* out = (float*)d_out;

    float *W2m, *h0, *h1, *h2, *hC;
    __nv_bfloat16 *W0hi, *W0lo, *W1hi, *W1lo, *xhi, *xlo, *h0hi, *h0lo;
    cudaGetSymbolAddress((void**)&W2m,  g_W2m);
    cudaGetSymbolAddress((void**)&W0hi, g_W0hi);
    cudaGetSymbolAddress((void**)&W0lo, g_W0lo);
    cudaGetSymbolAddress((void**)&W1hi, g_W1hi);
    cudaGetSymbolAddress((void**)&W1lo, g_W1lo);
    cudaGetSymbolAddress((void**)&xhi,  g_xhi);
    cudaGetSymbolAddress((void**)&xlo,  g_xlo);
    cudaGetSymbolAddress((void**)&h0hi, g_h0hi);
    cudaGetSymbolAddress((void**)&h0lo, g_h0lo);
    cudaGetSymbolAddress((void**)&h0,   g_h0);
    cudaGetSymbolAddress((void**)&h1,   g_h1);
    cudaGetSymbolAddress((void**)&h2,   g_h2);
    cudaGetSymbolAddress((void**)&hC,   g_hC);

    cudaFuncSetAttribute(gemm_wmma2<0>, cudaFuncAttributeMaxDynamicSharedMemorySize, WB_SMEM_BYTES);
    cudaFuncSetAttribute(gemm_wmma2<1>, cudaFuncAttributeMaxDynamicSharedMemorySize, WB_SMEM_BYTES);

    // adjacency -> CSR + degrees (single pass over the 256MB)
    build_csr<<<NROWS, 256>>>(adj);

    // pre-split x (independent of threshold)
    splitf<<<272, 1024>>>(x, xhi, xlo, NROWS * FDIM / 4);

    // exact global threshold (self-cleaning 2-level radix select)
    hist1_k<<<272, 1024>>>(S0, S1, S2);
    find_bin<<<1, 1024>>>();
    hist2_k<<<272, 1024>>>(S0, S1, S2);
    find_thr<<<1, 1024>>>();

    // masked weights, pre-split bf16 for W0/W1
    mask_all<<<272, 1024>>>(W0, S0, W1, S1, W2, S2, W0hi, W0lo, W1hi, W1lo, W2m);

    dim3 ggrid(HDIM / WB_BN, NROWS / WB_BM);   // (4, 64)
    // layer 0: h0 = x @ W0m^T, epilogue emits bf16 split directly
    gemm_wmma2<1><<<ggrid, 256, WB_SMEM_BYTES>>>(xhi, xlo, W0hi, W0lo, nullptr, h0hi, h0lo);
    // layer 1: h1 = h0 @ W1m^T (fp32 out)
    gemm_wmma2<0><<<ggrid, 256, WB_SMEM_BYTES>>>(h0hi, h0lo, W1hi, W1lo, h1, nullptr, nullptr);
    // aggregation: h2 = adj_n @ h1
    spmm512<<<NROWS, 256>>>(h1, h2);
    // pair_norm + relu -> h0 (reuse)
    colstats<<<128, 256>>>(h2);
    colfinal<<<1, 512>>>();
    norm_relu<<<4096, 256>>>(h2, h0);
    // layer 2: hC = h0 @ W2m^T  [8192,64] (fp32)
    sgemm_nt<128, 64, 16, 8, 4><<<dim3(CDIM / 64, NROWS / 128), 256>>>(h0, W2m, hC, NROWS, CDIM, HDIM);
    // final aggregation into output
    spmm64<<<NROWS, 64>>>(hC, out);
}